// round 8
// baseline (speedup 1.0000x reference)
#include <cuda_runtime.h>
#include <math.h>

#define NN 4096
#define MM 4096
#define DD 64
#define W_EPS 0.1f
#define INV_EPS 10.0f
#define ITERS 10
#define RPS 64
#define SLABS (NN / RPS)            // 64

#define XS_STRIDE 132
#define YS_STRIDE 68
#define XS_FLOATS (DD * XS_STRIDE)
#define YS_FLOATS (DD * YS_STRIDE)
#define SMEM_FLOATS (XS_FLOATS + YS_FLOATS)   // 51200 B

// ------------- static device scratch -------------
__device__ float d_C[(size_t)NN * MM];
__device__ float d_f[NN];
__device__ float d_g[MM];
__device__ float d_nx[NN];
__device__ float d_ny[MM];
__device__ float d_pm[SLABS * MM];
__device__ float d_ps[SLABS * MM];
__device__ double d_parts[2048];

// ------------- cache-policy accessors (evict_last via createpolicy + cache_hint) -------------
__device__ __forceinline__ unsigned long long evl_policy() {
    unsigned long long p;
    asm("createpolicy.fractional.L2::evict_last.b64 %0, 1.0;" : "=l"(p));
    return p;
}
__device__ __forceinline__ float4 ld_evl4(const float* p, unsigned long long pol) {
    float4 v;
    asm("ld.global.L2::cache_hint.v4.f32 {%0,%1,%2,%3}, [%4], %5;"
        : "=f"(v.x), "=f"(v.y), "=f"(v.z), "=f"(v.w) : "l"(p), "l"(pol));
    return v;
}
__device__ __forceinline__ float ld_evl(const float* p, unsigned long long pol) {
    float v;
    asm("ld.global.L2::cache_hint.f32 %0, [%1], %2;" : "=f"(v) : "l"(p), "l"(pol));
    return v;
}
__device__ __forceinline__ void st_evl4(float* p, float4 v, unsigned long long pol) {
    asm volatile("st.global.L2::cache_hint.v4.f32 [%0], {%1,%2,%3,%4}, %5;"
        :: "l"(p), "f"(v.x), "f"(v.y), "f"(v.z), "f"(v.w), "l"(pol) : "memory");
}
__device__ __forceinline__ void st_cs(float* p, float v) {
    asm volatile("st.global.cs.f32 [%0], %1;" :: "l"(p), "f"(v) : "memory");
}

// ------------- online-LSE helpers (m raw units, s = sum exp((v-m)/eps)) -------------
__device__ __forceinline__ void lse_merge(float& m1, float& s1, float m2, float s2) {
    float d = (m2 - m1) * INV_EPS;
    float e = __expf(-fabsf(d));
    if (d > 0.0f) { s1 = fmaf(s1, e, s2); m1 = m2; }
    else          { s1 = fmaf(s2, e, s1); }
}
__device__ __forceinline__ void lse_upd1(float& m, float& s, float v) {
    float d = (v - m) * INV_EPS;
    float e = __expf(-fabsf(d));
    bool up = d > 0.0f;
    s = up ? fmaf(s, e, 1.0f) : (s + e);
    m = up ? v : m;
}
__device__ __forceinline__ float4 f4sub(float4 a, float4 b) {
    return make_float4(a.x - b.x, a.y - b.y, a.z - b.z, a.w - b.w);
}
__device__ __forceinline__ float f4max(float4 a) {
    return fmaxf(fmaxf(a.x, a.y), fmaxf(a.z, a.w));
}
__device__ __forceinline__ float f4expsum(float4 a, float mn) {
    return __expf((a.x - mn) * INV_EPS) + __expf((a.y - mn) * INV_EPS)
         + __expf((a.z - mn) * INV_EPS) + __expf((a.w - mn) * INV_EPS);
}

// ================= prep: norms + g = 0 =================
__global__ void k_prep(const float* __restrict__ x, const float* __restrict__ y) {
    int gtid = blockIdx.x * 256 + threadIdx.x;
    if (gtid < MM) d_g[gtid] = 0.0f;
    int lane = threadIdx.x & 31;
    int row = gtid >> 5;                       // 1024 blocks * 8 warps = 8192 rows
    const float* src = (row < NN) ? (x + (size_t)row * DD)
                                  : (y + (size_t)(row - NN) * DD);
    float a = src[lane], c = src[lane + 32];
    float s = a * a + c * c;
    #pragma unroll
    for (int o = 16; o; o >>= 1) s += __shfl_xor_sync(0xffffffffu, s, o);
    if (lane == 0) { if (row < NN) d_nx[row] = s; else d_ny[row - NN] = s; }
}

// ================= cost: C = nx + ny - 2 x.y (128x64 tile, 8x4 micro) =================
extern __shared__ float sh[];
__global__ void __launch_bounds__(256)
k_cost(const float* __restrict__ x, const float* __restrict__ y) {
    float* xs = sh;
    float* ys = sh + XS_FLOATS;
    const int t = threadIdx.x;
    const int tx = t & 15, ty = t >> 4;
    int rowBase = blockIdx.y * 128, colBase = blockIdx.x * 64;
    unsigned long long pol = evl_policy();

    #pragma unroll
    for (int k2 = 0; k2 < 8; k2++) {
        int idx = t + 256 * k2;
        int rid = idx >> 4;
        int d4 = (idx & 15) << 2;
        float4 v = *(const float4*)(x + (size_t)(rowBase + rid) * DD + d4);
        xs[(d4 + 0) * XS_STRIDE + rid] = v.x;
        xs[(d4 + 1) * XS_STRIDE + rid] = v.y;
        xs[(d4 + 2) * XS_STRIDE + rid] = v.z;
        xs[(d4 + 3) * XS_STRIDE + rid] = v.w;
    }
    #pragma unroll
    for (int k2 = 0; k2 < 4; k2++) {
        int idx = t + 256 * k2;
        int cid = idx >> 4;
        int d4 = (idx & 15) << 2;
        float4 v = *(const float4*)(y + (size_t)(colBase + cid) * DD + d4);
        ys[(d4 + 0) * YS_STRIDE + cid] = v.x;
        ys[(d4 + 1) * YS_STRIDE + cid] = v.y;
        ys[(d4 + 2) * YS_STRIDE + cid] = v.z;
        ys[(d4 + 3) * YS_STRIDE + cid] = v.w;
    }
    __syncthreads();

    float acc[8][4];
    #pragma unroll
    for (int r = 0; r < 8; r++)
        #pragma unroll
        for (int c = 0; c < 4; c++) acc[r][c] = 0.0f;

    #pragma unroll 8
    for (int d = 0; d < DD; d++) {
        const float* xr = xs + d * XS_STRIDE + (ty << 3);
        float4 a0 = *(const float4*)xr;
        float4 a1 = *(const float4*)(xr + 4);
        float4 bb = *(const float4*)(ys + d * YS_STRIDE + (tx << 2));
        float av[8] = {a0.x, a0.y, a0.z, a0.w, a1.x, a1.y, a1.z, a1.w};
        float bv[4] = {bb.x, bb.y, bb.z, bb.w};
        #pragma unroll
        for (int r = 0; r < 8; r++)
            #pragma unroll
            for (int c = 0; c < 4; c++)
                acc[r][c] = fmaf(av[r], bv[c], acc[r][c]);
    }

    float4 ny4 = *(const float4*)(d_ny + colBase + (tx << 2));
    #pragma unroll
    for (int r = 0; r < 8; r++) {
        int row = rowBase + (ty << 3) + r;
        float nxr = d_nx[row];
        float4 o;
        o.x = nxr + ny4.x - 2.0f * acc[r][0];
        o.y = nxr + ny4.y - 2.0f * acc[r][1];
        o.z = nxr + ny4.z - 2.0f * acc[r][2];
        o.w = nxr + ny4.w - 2.0f * acc[r][3];
        st_evl4(d_C + (size_t)row * MM + colBase + (tx << 2), o, pol);
    }
}

// ================= row pass: 2 rows per block, register-resident exact LSE =================
__global__ void __launch_bounds__(256)
k_row(const float* __restrict__ p) {
    __shared__ float s_pm[16], s_ps[16];
    const int t = threadIdx.x;
    const int lane = t & 31;
    const int warp = t >> 5;
    const int r0 = blockIdx.x * 2;
    const float* C0 = d_C + (size_t)r0 * MM;
    const float* C1 = C0 + MM;
    unsigned long long pol = evl_policy();

    float4 v0[4], v1[4];
    #pragma unroll
    for (int w = 0; w < 4; w++) {
        int j = (t + 256 * w) * 4;
        float4 g4 = *(const float4*)(d_g + j);
        float4 c0 = ld_evl4(C0 + j, pol);
        float4 c1 = ld_evl4(C1 + j, pol);
        v0[w] = f4sub(g4, c0);
        v1[w] = f4sub(g4, c1);
    }
    float m0 = fmaxf(fmaxf(f4max(v0[0]), f4max(v0[1])), fmaxf(f4max(v0[2]), f4max(v0[3])));
    float m1 = fmaxf(fmaxf(f4max(v1[0]), f4max(v1[1])), fmaxf(f4max(v1[2]), f4max(v1[3])));
    float s0 = f4expsum(v0[0], m0) + f4expsum(v0[1], m0) + f4expsum(v0[2], m0) + f4expsum(v0[3], m0);
    float s1 = f4expsum(v1[0], m1) + f4expsum(v1[1], m1) + f4expsum(v1[2], m1) + f4expsum(v1[3], m1);

    #pragma unroll
    for (int o = 16; o; o >>= 1) {
        float mo = __shfl_down_sync(0xffffffffu, m0, o);
        float so = __shfl_down_sync(0xffffffffu, s0, o);
        lse_merge(m0, s0, mo, so);
        mo = __shfl_down_sync(0xffffffffu, m1, o);
        so = __shfl_down_sync(0xffffffffu, s1, o);
        lse_merge(m1, s1, mo, so);
    }
    if (lane == 0) {
        s_pm[warp] = m0;     s_ps[warp] = s0;
        s_pm[8 + warp] = m1; s_ps[8 + warp] = s1;
    }
    __syncthreads();
    if (warp == 0) {
        float mm = s_pm[lane & 15], ss = s_ps[lane & 15];
        #pragma unroll
        for (int o = 4; o; o >>= 1) {
            float mo = __shfl_down_sync(0xffffffffu, mm, o, 8);
            float so = __shfl_down_sync(0xffffffffu, ss, o, 8);
            lse_merge(mm, ss, mo, so);
        }
        if (lane == 0) d_f[r0]     = W_EPS * __logf(p[r0])     - mm - W_EPS * __logf(ss);
        if (lane == 8) d_f[r0 + 1] = W_EPS * __logf(p[r0 + 1]) - mm - W_EPS * __logf(ss);
    }
}

// ================= column partials: warp per (slab, 32-col group), 4 ILP chains =================
__global__ void __launch_bounds__(256)
k_colpart() {
    const int lane = threadIdx.x & 31;
    const int warp = threadIdx.x >> 5;
    const int u = blockIdx.x * 8 + warp;     // 1024 blocks * 8 warps = 8192 units
    const int slab = u >> 7;                 // 0..63
    const int col = ((u & 127) << 5) + lane;
    const float* Cp = d_C + (size_t)slab * RPS * MM + col;
    const float* fp = d_f + slab * RPS;
    unsigned long long pol = evl_policy();

    float m0 = -3.4e38f, s0 = 0.0f, m1 = -3.4e38f, s1 = 0.0f;
    float m2 = -3.4e38f, s2 = 0.0f, m3 = -3.4e38f, s3 = 0.0f;
    #pragma unroll 8
    for (int k = 0; k < RPS / 4; k++) {
        int r = k * 4;
        float c0 = ld_evl(Cp + (size_t)(r + 0) * MM, pol);
        float c1 = ld_evl(Cp + (size_t)(r + 1) * MM, pol);
        float c2 = ld_evl(Cp + (size_t)(r + 2) * MM, pol);
        float c3 = ld_evl(Cp + (size_t)(r + 3) * MM, pol);
        lse_upd1(m0, s0, fp[r + 0] - c0);
        lse_upd1(m1, s1, fp[r + 1] - c1);
        lse_upd1(m2, s2, fp[r + 2] - c2);
        lse_upd1(m3, s3, fp[r + 3] - c3);
    }
    lse_merge(m0, s0, m1, s1);
    lse_merge(m2, s2, m3, s3);
    lse_merge(m0, s0, m2, s2);
    d_pm[slab * MM + col] = m0;
    d_ps[slab * MM + col] = s0;
}

// ================= column finalize =================
__global__ void __launch_bounds__(256)
k_colfin(const float* __restrict__ q) {
    int j = blockIdx.x * 256 + threadIdx.x;   // 16 blocks
    float m0 = -3.4e38f, s0 = 0.0f, m1 = -3.4e38f, s1 = 0.0f;
    float m2 = -3.4e38f, s2 = 0.0f, m3 = -3.4e38f, s3 = 0.0f;
    #pragma unroll
    for (int k = 0; k < SLABS / 4; k++) {
        int k4 = k * 4;
        lse_merge(m0, s0, d_pm[(k4 + 0) * MM + j], d_ps[(k4 + 0) * MM + j]);
        lse_merge(m1, s1, d_pm[(k4 + 1) * MM + j], d_ps[(k4 + 1) * MM + j]);
        lse_merge(m2, s2, d_pm[(k4 + 2) * MM + j], d_ps[(k4 + 2) * MM + j]);
        lse_merge(m3, s3, d_pm[(k4 + 3) * MM + j], d_ps[(k4 + 3) * MM + j]);
    }
    lse_merge(m0, s0, m1, s1);
    lse_merge(m2, s2, m3, s3);
    lse_merge(m0, s0, m2, s2);
    d_g[j] = W_EPS * __logf(q[j]) - m0 - W_EPS * __logf(s0);
}

// ================= final: P = exp(S), cost partials =================
__global__ void __launch_bounds__(256)
k_final(float* __restrict__ Pout, int writeP) {
    __shared__ double dred[8];
    const int gsz = 2048 * 256;
    const int gtid = blockIdx.x * 256 + threadIdx.x;
    const int NV4 = (NN * MM) / 4;
    double csum = 0.0;
    #pragma unroll 4
    for (int v4 = gtid; v4 < NV4; v4 += gsz) {
        int base = v4 * 4;
        int i = base >> 12;
        int j = base & (MM - 1);
        float4 c4 = *(const float4*)(d_C + (size_t)base);
        float fi = d_f[i];
        float4 g4 = *(const float4*)(d_g + j);
        float p0 = __expf((fi + g4.x - c4.x) * INV_EPS);
        float p1 = __expf((fi + g4.y - c4.y) * INV_EPS);
        float p2 = __expf((fi + g4.z - c4.z) * INV_EPS);
        float p3 = __expf((fi + g4.w - c4.w) * INV_EPS);
        if (writeP) {   // Pout may be out+1 (4B aligned only) -> scalar streaming stores
            st_cs(Pout + base + 0, p0);
            st_cs(Pout + base + 1, p1);
            st_cs(Pout + base + 2, p2);
            st_cs(Pout + base + 3, p3);
        }
        csum += (double)(p0 * c4.x + p1 * c4.y + p2 * c4.z + p3 * c4.w);
    }
    #pragma unroll
    for (int o = 16; o; o >>= 1) csum += __shfl_xor_sync(0xffffffffu, csum, o);
    if ((threadIdx.x & 31) == 0) dred[threadIdx.x >> 5] = csum;
    __syncthreads();
    if (threadIdx.x == 0) {
        double sb = 0.0;
        #pragma unroll
        for (int k2 = 0; k2 < 8; k2++) sb += dred[k2];
        d_parts[blockIdx.x] = sb;
    }
}

__global__ void k_costfin(float* __restrict__ costslot) {
    __shared__ double fin[256];
    int t = threadIdx.x;
    double s = 0.0;
    for (int k2 = t; k2 < 2048; k2 += 256) s += d_parts[k2];
    fin[t] = s;
    __syncthreads();
    if (t == 0) {
        double tot = 0.0;
        for (int k2 = 0; k2 < 256; k2++) tot += fin[k2];
        costslot[0] = (float)tot;
    }
}

// ================= host launch =================
extern "C" void kernel_launch(void* const* d_in, const int* in_sizes, int n_in,
                              void* d_out, int out_size) {
    const float* x = (const float*)d_in[0];
    const float* y = (const float*)d_in[1];
    const float* p = (const float*)d_in[2];
    const float* q = (const float*)d_in[3];
    (void)in_sizes; (void)n_in;

    float* out = (float*)d_out;
    float* costslot = nullptr;
    float* Pout = nullptr;
    const long long total = (long long)NN * MM;
    if ((long long)out_size >= total + 1) { costslot = out; Pout = out + 1; }
    else if ((long long)out_size >= total) { Pout = out; }
    else { costslot = out; }

    size_t shbytes = SMEM_FLOATS * sizeof(float);
    static int shset = 0;
    if (!shset) {
        cudaFuncSetAttribute(k_cost, cudaFuncAttributeMaxDynamicSharedMemorySize, (int)shbytes);
        shset = 1;
    }

    k_prep<<<1024, 256>>>(x, y);
    k_cost<<<dim3(MM / 64, NN / 128), 256, shbytes>>>(x, y);

    for (int it = 0; it < ITERS; it++) {
        k_row<<<NN / 2, 256>>>(p);
        k_colpart<<<1024, 256>>>();
        k_colfin<<<16, 256>>>(q);
    }

    k_final<<<2048, 256>>>(Pout, Pout != nullptr);
    if (costslot) k_costfin<<<1, 256>>>(costslot);
}

// round 11
// speedup vs baseline: 1.1295x; 1.1295x over previous
#include <cuda_runtime.h>
#include <math.h>

#define NN 4096
#define MM 4096
#define DD 64
#define W_EPS 0.1f
#define INV_EPS 10.0f
#define ITERS 10
#define RPS 128
#define SLABS (NN / RPS)            // 32

// k_cost: two-phase K-split tile. Per phase: xs[32][132] + ys[32][132] floats = 33792 B
#define CT_STRIDE 132
#define CT_KH 32                    // d per phase

// ------------- static device scratch -------------
__device__ float d_C[(size_t)NN * MM];
__device__ float d_f[NN];
__device__ float d_g[MM];
__device__ float d_nx[NN];
__device__ float d_ny[MM];
__device__ float d_pm[SLABS * MM];
__device__ float d_ps[SLABS * MM];
__device__ double d_parts[2048];

// ------------- online-LSE helpers (m raw units, s = sum exp((v-m)/eps)) -------------
__device__ __forceinline__ void lse_merge(float& m1, float& s1, float m2, float s2) {
    float d = (m2 - m1) * INV_EPS;
    float e = __expf(-fabsf(d));
    if (d > 0.0f) { s1 = fmaf(s1, e, s2); m1 = m2; }
    else          { s1 = fmaf(s2, e, s1); }
}
__device__ __forceinline__ void lse_upd1(float& m, float& s, float v) {
    float d = (v - m) * INV_EPS;
    float e = __expf(-fabsf(d));
    bool up = d > 0.0f;
    s = up ? fmaf(s, e, 1.0f) : (s + e);
    m = up ? v : m;
}
__device__ __forceinline__ float4 f4sub(float4 a, float4 b) {
    return make_float4(a.x - b.x, a.y - b.y, a.z - b.z, a.w - b.w);
}
__device__ __forceinline__ float f4max(float4 a) {
    return fmaxf(fmaxf(a.x, a.y), fmaxf(a.z, a.w));
}
__device__ __forceinline__ float f4expsum(float4 a, float mn) {
    return __expf((a.x - mn) * INV_EPS) + __expf((a.y - mn) * INV_EPS)
         + __expf((a.z - mn) * INV_EPS) + __expf((a.w - mn) * INV_EPS);
}

// ================= prep: norms + g = 0 =================
__global__ void k_prep(const float* __restrict__ x, const float* __restrict__ y) {
    int gtid = blockIdx.x * 256 + threadIdx.x;
    if (gtid < MM) d_g[gtid] = 0.0f;
    int lane = threadIdx.x & 31;
    int row = gtid >> 5;                       // 1024 blocks * 8 warps = 8192 rows
    const float* src = (row < NN) ? (x + (size_t)row * DD)
                                  : (y + (size_t)(row - NN) * DD);
    float a = src[lane], c = src[lane + 32];
    float s = a * a + c * c;
    #pragma unroll
    for (int o = 16; o; o >>= 1) s += __shfl_xor_sync(0xffffffffu, s, o);
    if (lane == 0) { if (row < NN) d_nx[row] = s; else d_ny[row - NN] = s; }
}

// ====== cost: C = nx + ny - 2 x.y (128x128 tile, 8x8 micro, 2-phase K-split) ======
__global__ void __launch_bounds__(256)
k_cost(const float* __restrict__ x, const float* __restrict__ y) {
    __shared__ float xs[CT_KH * CT_STRIDE];   // [d_local][row]
    __shared__ float ys[CT_KH * CT_STRIDE];   // [d_local][col]
    const int t = threadIdx.x;
    const int tx = t & 15, ty = t >> 4;
    const int rowBase = blockIdx.y * 128, colBase = blockIdx.x * 128;

    float acc[8][8];
    #pragma unroll
    for (int r = 0; r < 8; r++)
        #pragma unroll
        for (int c = 0; c < 8; c++) acc[r][c] = 0.0f;

    #pragma unroll
    for (int ph = 0; ph < 2; ph++) {
        if (ph) __syncthreads();    // protect smem reuse between phases
        // load x slab: 128 rows x 32 d = 1024 float4 (4 per thread)
        #pragma unroll
        for (int k2 = 0; k2 < 4; k2++) {
            int idx = t + 256 * k2;           // 0..1023
            int rid = idx >> 3;               // 0..127
            int d4 = (idx & 7) << 2;          // 0..28
            float4 v = *(const float4*)(x + (size_t)(rowBase + rid) * DD + ph * CT_KH + d4);
            xs[(d4 + 0) * CT_STRIDE + rid] = v.x;
            xs[(d4 + 1) * CT_STRIDE + rid] = v.y;
            xs[(d4 + 2) * CT_STRIDE + rid] = v.z;
            xs[(d4 + 3) * CT_STRIDE + rid] = v.w;
        }
        // load y slab: 128 cols x 32 d
        #pragma unroll
        for (int k2 = 0; k2 < 4; k2++) {
            int idx = t + 256 * k2;
            int cid = idx >> 3;
            int d4 = (idx & 7) << 2;
            float4 v = *(const float4*)(y + (size_t)(colBase + cid) * DD + ph * CT_KH + d4);
            ys[(d4 + 0) * CT_STRIDE + cid] = v.x;
            ys[(d4 + 1) * CT_STRIDE + cid] = v.y;
            ys[(d4 + 2) * CT_STRIDE + cid] = v.z;
            ys[(d4 + 3) * CT_STRIDE + cid] = v.w;
        }
        __syncthreads();

        #pragma unroll 8
        for (int d = 0; d < CT_KH; d++) {
            const float* xr = xs + d * CT_STRIDE + (ty << 3);
            const float* yc = ys + d * CT_STRIDE + (tx << 3);
            float4 a0 = *(const float4*)xr;
            float4 a1 = *(const float4*)(xr + 4);
            float4 b0 = *(const float4*)yc;
            float4 b1 = *(const float4*)(yc + 4);
            float av[8] = {a0.x, a0.y, a0.z, a0.w, a1.x, a1.y, a1.z, a1.w};
            float bv[8] = {b0.x, b0.y, b0.z, b0.w, b1.x, b1.y, b1.z, b1.w};
            #pragma unroll
            for (int r = 0; r < 8; r++)
                #pragma unroll
                for (int c = 0; c < 8; c++)
                    acc[r][c] = fmaf(av[r], bv[c], acc[r][c]);
        }
    }

    float4 nyA = *(const float4*)(d_ny + colBase + (tx << 3));
    float4 nyB = *(const float4*)(d_ny + colBase + (tx << 3) + 4);
    #pragma unroll
    for (int r = 0; r < 8; r++) {
        int row = rowBase + (ty << 3) + r;
        float nxr = d_nx[row];
        float4 oA, oB;
        oA.x = nxr + nyA.x - 2.0f * acc[r][0];
        oA.y = nxr + nyA.y - 2.0f * acc[r][1];
        oA.z = nxr + nyA.z - 2.0f * acc[r][2];
        oA.w = nxr + nyA.w - 2.0f * acc[r][3];
        oB.x = nxr + nyB.x - 2.0f * acc[r][4];
        oB.y = nxr + nyB.y - 2.0f * acc[r][5];
        oB.z = nxr + nyB.z - 2.0f * acc[r][6];
        oB.w = nxr + nyB.w - 2.0f * acc[r][7];
        float* dst = d_C + (size_t)row * MM + colBase + (tx << 3);
        *(float4*)dst = oA;
        *(float4*)(dst + 4) = oB;
    }
}

// ================= row pass: 2 rows per block, register-resident exact LSE =================
__global__ void __launch_bounds__(256)
k_row(const float* __restrict__ p) {
    __shared__ float s_pm[16], s_ps[16];
    const int t = threadIdx.x;
    const int lane = t & 31;
    const int warp = t >> 5;
    const int r0 = blockIdx.x * 2;
    const float* C0 = d_C + (size_t)r0 * MM;
    const float* C1 = C0 + MM;

    float4 v0[4], v1[4];
    #pragma unroll
    for (int w = 0; w < 4; w++) {
        int j = (t + 256 * w) * 4;
        float4 g4 = *(const float4*)(d_g + j);
        float4 c0 = *(const float4*)(C0 + j);
        float4 c1 = *(const float4*)(C1 + j);
        v0[w] = f4sub(g4, c0);
        v1[w] = f4sub(g4, c1);
    }
    float m0 = fmaxf(fmaxf(f4max(v0[0]), f4max(v0[1])), fmaxf(f4max(v0[2]), f4max(v0[3])));
    float m1 = fmaxf(fmaxf(f4max(v1[0]), f4max(v1[1])), fmaxf(f4max(v1[2]), f4max(v1[3])));
    float s0 = f4expsum(v0[0], m0) + f4expsum(v0[1], m0) + f4expsum(v0[2], m0) + f4expsum(v0[3], m0);
    float s1 = f4expsum(v1[0], m1) + f4expsum(v1[1], m1) + f4expsum(v1[2], m1) + f4expsum(v1[3], m1);

    #pragma unroll
    for (int o = 16; o; o >>= 1) {
        float mo = __shfl_down_sync(0xffffffffu, m0, o);
        float so = __shfl_down_sync(0xffffffffu, s0, o);
        lse_merge(m0, s0, mo, so);
        mo = __shfl_down_sync(0xffffffffu, m1, o);
        so = __shfl_down_sync(0xffffffffu, s1, o);
        lse_merge(m1, s1, mo, so);
    }
    if (lane == 0) {
        s_pm[warp] = m0;     s_ps[warp] = s0;
        s_pm[8 + warp] = m1; s_ps[8 + warp] = s1;
    }
    __syncthreads();
    if (warp == 0) {
        float mm = s_pm[lane & 15], ss = s_ps[lane & 15];
        #pragma unroll
        for (int o = 4; o; o >>= 1) {
            float mo = __shfl_down_sync(0xffffffffu, mm, o, 8);
            float so = __shfl_down_sync(0xffffffffu, ss, o, 8);
            lse_merge(mm, ss, mo, so);
        }
        if (lane == 0) d_f[r0]     = W_EPS * __logf(p[r0])     - mm - W_EPS * __logf(ss);
        if (lane == 8) d_f[r0 + 1] = W_EPS * __logf(p[r0 + 1]) - mm - W_EPS * __logf(ss);
    }
}

// ================= column partials: warp per (slab, 32-col group), 4 ILP chains =================
__global__ void __launch_bounds__(256)
k_colpart() {
    const int lane = threadIdx.x & 31;
    const int warp = threadIdx.x >> 5;
    const int u = blockIdx.x * 8 + warp;     // 512 blocks * 8 warps = 4096 units
    const int slab = u >> 7;                 // 0..31
    const int col = ((u & 127) << 5) + lane;
    const float* Cp = d_C + (size_t)slab * RPS * MM + col;
    const float* fp = d_f + slab * RPS;

    float m0 = -3.4e38f, s0 = 0.0f, m1 = -3.4e38f, s1 = 0.0f;
    float m2 = -3.4e38f, s2 = 0.0f, m3 = -3.4e38f, s3 = 0.0f;
    #pragma unroll 8
    for (int k = 0; k < RPS / 4; k++) {
        int r = k * 4;
        float c0 = Cp[(size_t)(r + 0) * MM];
        float c1 = Cp[(size_t)(r + 1) * MM];
        float c2 = Cp[(size_t)(r + 2) * MM];
        float c3 = Cp[(size_t)(r + 3) * MM];
        lse_upd1(m0, s0, fp[r + 0] - c0);
        lse_upd1(m1, s1, fp[r + 1] - c1);
        lse_upd1(m2, s2, fp[r + 2] - c2);
        lse_upd1(m3, s3, fp[r + 3] - c3);
    }
    lse_merge(m0, s0, m1, s1);
    lse_merge(m2, s2, m3, s3);
    lse_merge(m0, s0, m2, s2);
    d_pm[slab * MM + col] = m0;
    d_ps[slab * MM + col] = s0;
}

// ================= column finalize =================
__global__ void __launch_bounds__(256)
k_colfin(const float* __restrict__ q) {
    int j = blockIdx.x * 256 + threadIdx.x;   // 16 blocks
    float m0 = -3.4e38f, s0 = 0.0f, m1 = -3.4e38f, s1 = 0.0f;
    float m2 = -3.4e38f, s2 = 0.0f, m3 = -3.4e38f, s3 = 0.0f;
    #pragma unroll
    for (int k = 0; k < SLABS / 4; k++) {
        int k4 = k * 4;
        lse_merge(m0, s0, d_pm[(k4 + 0) * MM + j], d_ps[(k4 + 0) * MM + j]);
        lse_merge(m1, s1, d_pm[(k4 + 1) * MM + j], d_ps[(k4 + 1) * MM + j]);
        lse_merge(m2, s2, d_pm[(k4 + 2) * MM + j], d_ps[(k4 + 2) * MM + j]);
        lse_merge(m3, s3, d_pm[(k4 + 3) * MM + j], d_ps[(k4 + 3) * MM + j]);
    }
    lse_merge(m0, s0, m1, s1);
    lse_merge(m2, s2, m3, s3);
    lse_merge(m0, s0, m2, s2);
    d_g[j] = W_EPS * __logf(q[j]) - m0 - W_EPS * __logf(s0);
}

// ================= final: P = exp(S), cost partials =================
__global__ void __launch_bounds__(256)
k_final(float* __restrict__ Pout, int writeP) {
    __shared__ double dred[8];
    const int gsz = 2048 * 256;
    const int gtid = blockIdx.x * 256 + threadIdx.x;
    const int NV4 = (NN * MM) / 4;
    double csum = 0.0;
    #pragma unroll 4
    for (int v4 = gtid; v4 < NV4; v4 += gsz) {
        int base = v4 * 4;
        int i = base >> 12;
        int j = base & (MM - 1);
        float4 c4 = *(const float4*)(d_C + (size_t)base);
        float fi = d_f[i];
        float4 g4 = *(const float4*)(d_g + j);
        float p0 = __expf((fi + g4.x - c4.x) * INV_EPS);
        float p1 = __expf((fi + g4.y - c4.y) * INV_EPS);
        float p2 = __expf((fi + g4.z - c4.z) * INV_EPS);
        float p3 = __expf((fi + g4.w - c4.w) * INV_EPS);
        if (writeP) {   // Pout may be out+1 (4B aligned only) -> scalar stores
            Pout[base + 0] = p0; Pout[base + 1] = p1;
            Pout[base + 2] = p2; Pout[base + 3] = p3;
        }
        csum += (double)(p0 * c4.x + p1 * c4.y + p2 * c4.z + p3 * c4.w);
    }
    #pragma unroll
    for (int o = 16; o; o >>= 1) csum += __shfl_xor_sync(0xffffffffu, csum, o);
    if ((threadIdx.x & 31) == 0) dred[threadIdx.x >> 5] = csum;
    __syncthreads();
    if (threadIdx.x == 0) {
        double sb = 0.0;
        #pragma unroll
        for (int k2 = 0; k2 < 8; k2++) sb += dred[k2];
        d_parts[blockIdx.x] = sb;
    }
}

__global__ void k_costfin(float* __restrict__ costslot) {
    __shared__ double fin[256];
    int t = threadIdx.x;
    double s = 0.0;
    for (int k2 = t; k2 < 2048; k2 += 256) s += d_parts[k2];
    fin[t] = s;
    __syncthreads();
    if (t == 0) {
        double tot = 0.0;
        for (int k2 = 0; k2 < 256; k2++) tot += fin[k2];
        costslot[0] = (float)tot;
    }
}

// ================= host launch =================
extern "C" void kernel_launch(void* const* d_in, const int* in_sizes, int n_in,
                              void* d_out, int out_size) {
    const float* x = (const float*)d_in[0];
    const float* y = (const float*)d_in[1];
    const float* p = (const float*)d_in[2];
    const float* q = (const float*)d_in[3];
    (void)in_sizes; (void)n_in;

    float* out = (float*)d_out;
    float* costslot = nullptr;
    float* Pout = nullptr;
    const long long total = (long long)NN * MM;
    if ((long long)out_size >= total + 1) { costslot = out; Pout = out + 1; }
    else if ((long long)out_size >= total) { Pout = out; }
    else { costslot = out; }

    k_prep<<<1024, 256>>>(x, y);
    k_cost<<<dim3(MM / 128, NN / 128), 256>>>(x, y);

    for (int it = 0; it < ITERS; it++) {
        k_row<<<NN / 2, 256>>>(p);
        k_colpart<<<512, 256>>>();
        k_colfin<<<16, 256>>>(q);
    }

    k_final<<<2048, 256>>>(Pout, Pout != nullptr);
    if (costslot) k_costfin<<<1, 256>>>(costslot);
}

// round 12
// speedup vs baseline: 1.1470x; 1.0155x over previous
#include <cuda_runtime.h>
#include <math.h>

#define NN 4096
#define MM 4096
#define DD 64
#define W_EPS 0.1f
#define INV_EPS 10.0f
#define ITERS 10
#define RPS 128
#define SLABS (NN / RPS)            // 32

// k_cost: two-phase K-split tile. Per phase: xs[32][132] + ys[32][132] floats = 33792 B
#define CT_STRIDE 132
#define CT_KH 32                    // d per phase

// ------------- static device scratch -------------
__device__ float d_C[(size_t)NN * MM];
__device__ float d_f[NN];
__device__ float d_g[MM];
__device__ float d_nx[NN];
__device__ float d_ny[MM];
__device__ float d_pm[SLABS * MM];
__device__ float d_ps[SLABS * MM];
__device__ double d_parts[2048];

// ------------- online-LSE helpers (m raw units, s = sum exp((v-m)/eps)) -------------
__device__ __forceinline__ void lse_merge(float& m1, float& s1, float m2, float s2) {
    float d = (m2 - m1) * INV_EPS;
    float e = __expf(-fabsf(d));
    if (d > 0.0f) { s1 = fmaf(s1, e, s2); m1 = m2; }
    else          { s1 = fmaf(s2, e, s1); }
}
__device__ __forceinline__ void lse_upd1(float& m, float& s, float v) {
    float d = (v - m) * INV_EPS;
    float e = __expf(-fabsf(d));
    bool up = d > 0.0f;
    s = up ? fmaf(s, e, 1.0f) : (s + e);
    m = up ? v : m;
}
__device__ __forceinline__ float4 f4sub(float4 a, float4 b) {
    return make_float4(a.x - b.x, a.y - b.y, a.z - b.z, a.w - b.w);
}
__device__ __forceinline__ float f4max(float4 a) {
    return fmaxf(fmaxf(a.x, a.y), fmaxf(a.z, a.w));
}
__device__ __forceinline__ float f4expsum(float4 a, float mn) {
    return __expf((a.x - mn) * INV_EPS) + __expf((a.y - mn) * INV_EPS)
         + __expf((a.z - mn) * INV_EPS) + __expf((a.w - mn) * INV_EPS);
}

// ================= prep: norms + g = 0 =================
__global__ void k_prep(const float* __restrict__ x, const float* __restrict__ y) {
    int gtid = blockIdx.x * 256 + threadIdx.x;
    if (gtid < MM) d_g[gtid] = 0.0f;
    int lane = threadIdx.x & 31;
    int row = gtid >> 5;                       // 1024 blocks * 8 warps = 8192 rows
    const float* src = (row < NN) ? (x + (size_t)row * DD)
                                  : (y + (size_t)(row - NN) * DD);
    float a = src[lane], c = src[lane + 32];
    float s = a * a + c * c;
    #pragma unroll
    for (int o = 16; o; o >>= 1) s += __shfl_xor_sync(0xffffffffu, s, o);
    if (lane == 0) { if (row < NN) d_nx[row] = s; else d_ny[row - NN] = s; }
}

// ====== cost: C = nx + ny - 2 x.y (128x128 tile, split 8x8 micro, 2-phase K) ======
// Thread (tx,ty) owns rows {ty*4..+3, ty*4+64..+67} x cols {tx*4..+3, tx*4+64..+67}.
// b-operand LDS.128 per 8-lane phase hits banks 0,4,...,28 -> conflict-free.
__global__ void __launch_bounds__(256)
k_cost(const float* __restrict__ x, const float* __restrict__ y) {
    __shared__ float xs[CT_KH * CT_STRIDE];   // [d_local][row]
    __shared__ float ys[CT_KH * CT_STRIDE];   // [d_local][col]
    const int t = threadIdx.x;
    const int tx = t & 15, ty = t >> 4;
    const int rowBase = blockIdx.y * 128, colBase = blockIdx.x * 128;

    float acc[8][8];
    #pragma unroll
    for (int r = 0; r < 8; r++)
        #pragma unroll
        for (int c = 0; c < 8; c++) acc[r][c] = 0.0f;

    #pragma unroll
    for (int ph = 0; ph < 2; ph++) {
        if (ph) __syncthreads();    // protect smem reuse between phases
        // load x slab: 128 rows x 32 d = 1024 float4 (4 per thread)
        #pragma unroll
        for (int k2 = 0; k2 < 4; k2++) {
            int idx = t + 256 * k2;           // 0..1023
            int rid = idx >> 3;               // 0..127
            int d4 = (idx & 7) << 2;          // 0..28
            float4 v = *(const float4*)(x + (size_t)(rowBase + rid) * DD + ph * CT_KH + d4);
            xs[(d4 + 0) * CT_STRIDE + rid] = v.x;
            xs[(d4 + 1) * CT_STRIDE + rid] = v.y;
            xs[(d4 + 2) * CT_STRIDE + rid] = v.z;
            xs[(d4 + 3) * CT_STRIDE + rid] = v.w;
        }
        // load y slab: 128 cols x 32 d
        #pragma unroll
        for (int k2 = 0; k2 < 4; k2++) {
            int idx = t + 256 * k2;
            int cid = idx >> 3;
            int d4 = (idx & 7) << 2;
            float4 v = *(const float4*)(y + (size_t)(colBase + cid) * DD + ph * CT_KH + d4);
            ys[(d4 + 0) * CT_STRIDE + cid] = v.x;
            ys[(d4 + 1) * CT_STRIDE + cid] = v.y;
            ys[(d4 + 2) * CT_STRIDE + cid] = v.z;
            ys[(d4 + 3) * CT_STRIDE + cid] = v.w;
        }
        __syncthreads();

        #pragma unroll 8
        for (int d = 0; d < CT_KH; d++) {
            const float* xr = xs + d * CT_STRIDE;
            const float* yc = ys + d * CT_STRIDE;
            float4 a0 = *(const float4*)(xr + (ty << 2));          // rows ty*4..+3
            float4 a1 = *(const float4*)(xr + (ty << 2) + 64);     // rows ty*4+64..+67
            float4 b0 = *(const float4*)(yc + (tx << 2));          // cols tx*4..+3
            float4 b1 = *(const float4*)(yc + (tx << 2) + 64);     // cols tx*4+64..+67
            float av[8] = {a0.x, a0.y, a0.z, a0.w, a1.x, a1.y, a1.z, a1.w};
            float bv[8] = {b0.x, b0.y, b0.z, b0.w, b1.x, b1.y, b1.z, b1.w};
            #pragma unroll
            for (int r = 0; r < 8; r++)
                #pragma unroll
                for (int c = 0; c < 8; c++)
                    acc[r][c] = fmaf(av[r], bv[c], acc[r][c]);
        }
    }

    float4 nyA = *(const float4*)(d_ny + colBase + (tx << 2));
    float4 nyB = *(const float4*)(d_ny + colBase + (tx << 2) + 64);
    #pragma unroll
    for (int rg = 0; rg < 2; rg++) {
        #pragma unroll
        for (int r4 = 0; r4 < 4; r4++) {
            int r = rg * 4 + r4;
            int row = rowBase + (ty << 2) + rg * 64 + r4;
            float nxr = d_nx[row];
            float4 oA, oB;
            oA.x = nxr + nyA.x - 2.0f * acc[r][0];
            oA.y = nxr + nyA.y - 2.0f * acc[r][1];
            oA.z = nxr + nyA.z - 2.0f * acc[r][2];
            oA.w = nxr + nyA.w - 2.0f * acc[r][3];
            oB.x = nxr + nyB.x - 2.0f * acc[r][4];
            oB.y = nxr + nyB.y - 2.0f * acc[r][5];
            oB.z = nxr + nyB.z - 2.0f * acc[r][6];
            oB.w = nxr + nyB.w - 2.0f * acc[r][7];
            float* dst = d_C + (size_t)row * MM + colBase + (tx << 2);
            *(float4*)dst = oA;
            *(float4*)(dst + 64) = oB;
        }
    }
}

// ================= row pass: 2 rows per block, register-resident exact LSE =================
__global__ void __launch_bounds__(256)
k_row(const float* __restrict__ p) {
    __shared__ float s_pm[16], s_ps[16];
    const int t = threadIdx.x;
    const int lane = t & 31;
    const int warp = t >> 5;
    const int r0 = blockIdx.x * 2;
    const float* C0 = d_C + (size_t)r0 * MM;
    const float* C1 = C0 + MM;

    float4 v0[4], v1[4];
    #pragma unroll
    for (int w = 0; w < 4; w++) {
        int j = (t + 256 * w) * 4;
        float4 g4 = *(const float4*)(d_g + j);
        float4 c0 = *(const float4*)(C0 + j);
        float4 c1 = *(const float4*)(C1 + j);
        v0[w] = f4sub(g4, c0);
        v1[w] = f4sub(g4, c1);
    }
    float m0 = fmaxf(fmaxf(f4max(v0[0]), f4max(v0[1])), fmaxf(f4max(v0[2]), f4max(v0[3])));
    float m1 = fmaxf(fmaxf(f4max(v1[0]), f4max(v1[1])), fmaxf(f4max(v1[2]), f4max(v1[3])));
    float s0 = f4expsum(v0[0], m0) + f4expsum(v0[1], m0) + f4expsum(v0[2], m0) + f4expsum(v0[3], m0);
    float s1 = f4expsum(v1[0], m1) + f4expsum(v1[1], m1) + f4expsum(v1[2], m1) + f4expsum(v1[3], m1);

    #pragma unroll
    for (int o = 16; o; o >>= 1) {
        float mo = __shfl_down_sync(0xffffffffu, m0, o);
        float so = __shfl_down_sync(0xffffffffu, s0, o);
        lse_merge(m0, s0, mo, so);
        mo = __shfl_down_sync(0xffffffffu, m1, o);
        so = __shfl_down_sync(0xffffffffu, s1, o);
        lse_merge(m1, s1, mo, so);
    }
    if (lane == 0) {
        s_pm[warp] = m0;     s_ps[warp] = s0;
        s_pm[8 + warp] = m1; s_ps[8 + warp] = s1;
    }
    __syncthreads();
    if (warp == 0) {
        float mm = s_pm[lane & 15], ss = s_ps[lane & 15];
        #pragma unroll
        for (int o = 4; o; o >>= 1) {
            float mo = __shfl_down_sync(0xffffffffu, mm, o, 8);
            float so = __shfl_down_sync(0xffffffffu, ss, o, 8);
            lse_merge(mm, ss, mo, so);
        }
        if (lane == 0) d_f[r0]     = W_EPS * __logf(p[r0])     - mm - W_EPS * __logf(ss);
        if (lane == 8) d_f[r0 + 1] = W_EPS * __logf(p[r0 + 1]) - mm - W_EPS * __logf(ss);
    }
}

// ================= column partials: warp per (slab, 32-col group), 4 ILP chains =================
__global__ void __launch_bounds__(256)
k_colpart() {
    const int lane = threadIdx.x & 31;
    const int warp = threadIdx.x >> 5;
    const int u = blockIdx.x * 8 + warp;     // 512 blocks * 8 warps = 4096 units
    const int slab = u >> 7;                 // 0..31
    const int col = ((u & 127) << 5) + lane;
    const float* Cp = d_C + (size_t)slab * RPS * MM + col;
    const float* fp = d_f + slab * RPS;

    float m0 = -3.4e38f, s0 = 0.0f, m1 = -3.4e38f, s1 = 0.0f;
    float m2 = -3.4e38f, s2 = 0.0f, m3 = -3.4e38f, s3 = 0.0f;
    #pragma unroll 8
    for (int k = 0; k < RPS / 4; k++) {
        int r = k * 4;
        float c0 = Cp[(size_t)(r + 0) * MM];
        float c1 = Cp[(size_t)(r + 1) * MM];
        float c2 = Cp[(size_t)(r + 2) * MM];
        float c3 = Cp[(size_t)(r + 3) * MM];
        lse_upd1(m0, s0, fp[r + 0] - c0);
        lse_upd1(m1, s1, fp[r + 1] - c1);
        lse_upd1(m2, s2, fp[r + 2] - c2);
        lse_upd1(m3, s3, fp[r + 3] - c3);
    }
    lse_merge(m0, s0, m1, s1);
    lse_merge(m2, s2, m3, s3);
    lse_merge(m0, s0, m2, s2);
    d_pm[slab * MM + col] = m0;
    d_ps[slab * MM + col] = s0;
}

// ================= column finalize =================
__global__ void __launch_bounds__(256)
k_colfin(const float* __restrict__ q) {
    int j = blockIdx.x * 256 + threadIdx.x;   // 16 blocks
    float m0 = -3.4e38f, s0 = 0.0f, m1 = -3.4e38f, s1 = 0.0f;
    float m2 = -3.4e38f, s2 = 0.0f, m3 = -3.4e38f, s3 = 0.0f;
    #pragma unroll
    for (int k = 0; k < SLABS / 4; k++) {
        int k4 = k * 4;
        lse_merge(m0, s0, d_pm[(k4 + 0) * MM + j], d_ps[(k4 + 0) * MM + j]);
        lse_merge(m1, s1, d_pm[(k4 + 1) * MM + j], d_ps[(k4 + 1) * MM + j]);
        lse_merge(m2, s2, d_pm[(k4 + 2) * MM + j], d_ps[(k4 + 2) * MM + j]);
        lse_merge(m3, s3, d_pm[(k4 + 3) * MM + j], d_ps[(k4 + 3) * MM + j]);
    }
    lse_merge(m0, s0, m1, s1);
    lse_merge(m2, s2, m3, s3);
    lse_merge(m0, s0, m2, s2);
    d_g[j] = W_EPS * __logf(q[j]) - m0 - W_EPS * __logf(s0);
}

// ================= final: P = exp(S), cost partials =================
__global__ void __launch_bounds__(256)
k_final(float* __restrict__ Pout, int writeP) {
    __shared__ double dred[8];
    const int gsz = 2048 * 256;
    const int gtid = blockIdx.x * 256 + threadIdx.x;
    const int NV4 = (NN * MM) / 4;
    double csum = 0.0;
    #pragma unroll 4
    for (int v4 = gtid; v4 < NV4; v4 += gsz) {
        int base = v4 * 4;
        int i = base >> 12;
        int j = base & (MM - 1);
        float4 c4 = *(const float4*)(d_C + (size_t)base);
        float fi = d_f[i];
        float4 g4 = *(const float4*)(d_g + j);
        float p0 = __expf((fi + g4.x - c4.x) * INV_EPS);
        float p1 = __expf((fi + g4.y - c4.y) * INV_EPS);
        float p2 = __expf((fi + g4.z - c4.z) * INV_EPS);
        float p3 = __expf((fi + g4.w - c4.w) * INV_EPS);
        if (writeP) {   // Pout may be out+1 (4B aligned only) -> scalar stores
            Pout[base + 0] = p0; Pout[base + 1] = p1;
            Pout[base + 2] = p2; Pout[base + 3] = p3;
        }
        csum += (double)(p0 * c4.x + p1 * c4.y + p2 * c4.z + p3 * c4.w);
    }
    #pragma unroll
    for (int o = 16; o; o >>= 1) csum += __shfl_xor_sync(0xffffffffu, csum, o);
    if ((threadIdx.x & 31) == 0) dred[threadIdx.x >> 5] = csum;
    __syncthreads();
    if (threadIdx.x == 0) {
        double sb = 0.0;
        #pragma unroll
        for (int k2 = 0; k2 < 8; k2++) sb += dred[k2];
        d_parts[blockIdx.x] = sb;
    }
}

__global__ void k_costfin(float* __restrict__ costslot) {
    __shared__ double fin[256];
    int t = threadIdx.x;
    double s = 0.0;
    for (int k2 = t; k2 < 2048; k2 += 256) s += d_parts[k2];
    fin[t] = s;
    __syncthreads();
    if (t == 0) {
        double tot = 0.0;
        for (int k2 = 0; k2 < 256; k2++) tot += fin[k2];
        costslot[0] = (float)tot;
    }
}

// ================= host launch =================
extern "C" void kernel_launch(void* const* d_in, const int* in_sizes, int n_in,
                              void* d_out, int out_size) {
    const float* x = (const float*)d_in[0];
    const float* y = (const float*)d_in[1];
    const float* p = (const float*)d_in[2];
    const float* q = (const float*)d_in[3];
    (void)in_sizes; (void)n_in;

    float* out = (float*)d_out;
    float* costslot = nullptr;
    float* Pout = nullptr;
    const long long total = (long long)NN * MM;
    if ((long long)out_size >= total + 1) { costslot = out; Pout = out + 1; }
    else if ((long long)out_size >= total) { Pout = out; }
    else { costslot = out; }

    k_prep<<<1024, 256>>>(x, y);
    k_cost<<<dim3(MM / 128, NN / 128), 256>>>(x, y);

    for (int it = 0; it < ITERS; it++) {
        k_row<<<NN / 2, 256>>>(p);
        k_colpart<<<512, 256>>>();
        k_colfin<<<16, 256>>>(q);
    }

    k_final<<<2048, 256>>>(Pout, Pout != nullptr);
    if (costslot) k_costfin<<<1, 256>>>(costslot);
}